// round 14
// baseline (speedup 1.0000x reference)
#include <cuda_runtime.h>
#include <cuda_bf16.h>
#include <stdint.h>
#include <math.h>

// RoIPool: input [N,256,50,50] f32, rois [R,5] f32, out [R,256,7,7] f32.
// spatial_scale=1/16; torchvision MaxRoiPool semantics (round-half-even,
// roi size >= 1, floor/ceil bin edges clipped to [0,W]/[0,H], empty bin -> 0).
//
// Design:
//  1) transpose NCHW -> NHWC (channels contiguous)
//  2) main: block = (roi, 128-ch half, bin-half), 800 threads = 25 warps.
//     Each warp = ONE bin x 128 channels (32 lanes x float4 = LDG.128),
//     warp-uniform bounds, all window loads independent (high MLP).
//     ~25k compute warps total for latency hiding.
//     Output staged [bin][128ch] in smem (STS.128), cooperative coalesced
//     copyout to [c][bin].

typedef unsigned int u32;

#define PH 7
#define PW 7
#define BINS 49
#define SCALE 0.0625f
#define C_ 256
#define H_ 50
#define W_ 50
#define HW_ (H_ * W_)
#define CHW_ (C_ * HW_)
#define MAXN 4
#define C4_ (C_ / 4)     // 64 float4 per cell

__device__ float g_inT[MAXN * HW_ * C_];   // [N][H][W][C]

// ---------------- transpose [N,C,HW] -> [N,HW,C] ----------------
__global__ void transpose_k(const float* __restrict__ in) {
    __shared__ float t[32][33];
    int b  = blockIdx.z;
    int s0 = blockIdx.x * 32;   // hw tile
    int c0 = blockIdx.y * 32;   // channel tile
    int x = threadIdx.x, y = threadIdx.y;

#pragma unroll
    for (int j = 0; j < 32; j += 8) {
        int c = c0 + y + j, s = s0 + x;
        if (s < HW_) t[y + j][x] = in[b * CHW_ + c * HW_ + s];
    }
    __syncthreads();
#pragma unroll
    for (int j = 0; j < 32; j += 8) {
        int s = s0 + y + j, c = c0 + x;
        if (s < HW_) g_inT[b * CHW_ + s * C_ + c] = t[x][y + j];
    }
}

// ---------------- main pooling ----------------
#define ROW 132   // smem row stride (floats) for 128 channels + pad

template <int NB>
__device__ __forceinline__ void pool_body(int bin0) {
    extern __shared__ float smem_raw[];
    // layout: sOut[NB_MAX=25][ROW] then 28 ints of edges/base
    float* sOut = smem_raw;
    int*   sEdg = (int*)(smem_raw + 25 * ROW);   // ws[7] we[7] hs[7] he[7] base

    int r    = blockIdx.x;
    int half = blockIdx.y;
    int tid  = threadIdx.x;
    int wid  = tid >> 5;
    int lane = tid & 31;

    if (wid < NB) {
        int bin = bin0 + wid;
        int ph = bin / PW;
        int pw = bin - ph * PW;
        int ws = sEdg[pw], we = sEdg[7 + pw];
        int h0 = sEdg[14 + ph], h1 = sEdg[21 + ph];

        const float4* base = (const float4*)g_inT + sEdg[28] + half * 32 + lane;
        float4 a = make_float4(-INFINITY, -INFINITY, -INFINITY, -INFINITY);
        for (int h = h0; h < h1; ++h) {
            const float4* rp = base + (h * W_ + ws) * C4_;
            for (int w = ws; w < we; ++w) {
                float4 v = *rp;
                a.x = fmaxf(a.x, v.x);
                a.y = fmaxf(a.y, v.y);
                a.z = fmaxf(a.z, v.z);
                a.w = fmaxf(a.w, v.w);
                rp += C4_;
            }
        }
        if (h1 <= h0 || we <= ws) a = make_float4(0.f, 0.f, 0.f, 0.f);
        *(float4*)(sOut + wid * ROW + lane * 4) = a;   // STS.128
    }
    __syncthreads();

    // copyout: out[r][half*128 + cc][bin0 + b], b in [0,NB)
    float* outp = ((float*)0) ;
    (void)outp;
}

template <int NB>
__global__ void __launch_bounds__(800) roipool_k(const float* __restrict__ rois,
                                                 float* __restrict__ out,
                                                 int bin0) {
    extern __shared__ float smem_raw[];
    float* sOut = smem_raw;
    int*   sEdg = (int*)(smem_raw + 25 * ROW);

    int r    = blockIdx.x;
    int half = blockIdx.y;
    int tid  = threadIdx.x;
    int wid  = tid >> 5;
    int lane = tid & 31;

    // ---- bin edges (threads 0..6) ----
    if (tid < PW) {
        const float* roi = rois + r * 5;
        float f0 = roi[0], f1 = roi[1], f2 = roi[2], f3 = roi[3], f4 = roi[4];
        int x1 = (int)rintf(f1 * SCALE);
        int y1 = (int)rintf(f2 * SCALE);
        int x2 = (int)rintf(f3 * SCALE);
        int y2 = (int)rintf(f4 * SCALE);
        int rw = max(x2 - x1 + 1, 1);
        int rh = max(y2 - y1 + 1, 1);
        float bw = (float)rw * (1.0f / PW);
        float bh = (float)rh * (1.0f / PH);
        int j = tid;
        sEdg[j]      = min(max((int)floorf((float)j * bw) + x1, 0), W_);
        sEdg[7 + j]  = min(max((int)ceilf((float)(j + 1) * bw) + x1, 0), W_);
        sEdg[14 + j] = min(max((int)floorf((float)j * bh) + y1, 0), H_);
        sEdg[21 + j] = min(max((int)ceilf((float)(j + 1) * bh) + y1, 0), H_);
        if (tid == 0) sEdg[28] = (int)f0 * (CHW_ / 4);   // base in float4 units
    }
    __syncthreads();

    // ---- compute: warp = one bin ----
    if (wid < NB) {
        int bin = bin0 + wid;
        int ph = bin / PW;
        int pw = bin - ph * PW;
        int ws = sEdg[pw], we = sEdg[7 + pw];
        int h0 = sEdg[14 + ph], h1 = sEdg[21 + ph];

        const float4* base = (const float4*)g_inT + sEdg[28] + half * 32 + lane;
        float4 a = make_float4(-INFINITY, -INFINITY, -INFINITY, -INFINITY);
        for (int h = h0; h < h1; ++h) {
            const float4* rp = base + (h * W_ + ws) * C4_;
            for (int w = ws; w < we; ++w) {
                float4 v = *rp;
                a.x = fmaxf(a.x, v.x);
                a.y = fmaxf(a.y, v.y);
                a.z = fmaxf(a.z, v.z);
                a.w = fmaxf(a.w, v.w);
                rp += C4_;
            }
        }
        if (h1 <= h0 || we <= ws) a = make_float4(0.f, 0.f, 0.f, 0.f);
        *(float4*)(sOut + wid * ROW + lane * 4) = a;   // STS.128
    }
    __syncthreads();

    // ---- copyout: out[r][half*128 + cc][bin0 + b] ----
    float* outp = out + ((size_t)r * C_ + half * 128) * BINS + bin0;
    for (int e = tid; e < 128 * NB; e += 800) {
        u32 cc = (u32)e / NB;            // compile-time NB -> magic mul
        u32 b  = (u32)e - cc * NB;
        outp[cc * BINS + b] = sOut[b * ROW + cc];
    }
}

// ---------------- launch ----------------
extern "C" void kernel_launch(void* const* d_in, const int* in_sizes, int n_in,
                              void* d_out, int out_size) {
    const float* input = (const float*)d_in[0];
    const float* rois  = (const float*)d_in[1];
    float* out = (float*)d_out;

    int N = in_sizes[0] / CHW_;
    int R = in_sizes[1] / 5;

    dim3 tg((HW_ + 31) / 32, C_ / 32, N);
    transpose_k<<<tg, dim3(32, 8)>>>(input);

    size_t smem = 25 * ROW * sizeof(float) + 32 * sizeof(int);
    roipool_k<25><<<dim3(R, 2), 800, smem>>>(rois, out, 0);
    roipool_k<24><<<dim3(R, 2), 800, smem>>>(rois, out, 25);
}